// round 8
// baseline (speedup 1.0000x reference)
#include <cuda_runtime.h>
#include <cuda_bf16.h>
#include <cstdint>

// ============================================================
// Problem constants
// ============================================================
#define BB    32
#define HID   128
#define ATTN  128
#define S_TOTAL   8192
#define TILE_S    128
#define TILES_PB  (S_TOTAL / TILE_S) // 64
#define CPB       8
#define TILES_PER_CTA (TILES_PB / CPB) // 8
#define NCTA      (BB * CPB)         // 256

// bf16 tile [128 rows][128 cols] with 16B row pad
#define PITCH_H   136
#define PITCH_B   (PITCH_H * 2)      // 272
#define TILE_BYTES (128 * PITCH_B)   // 34816

// SMEM layout (bytes)
#define SMEM_RED    0                      // float[8] (+ combine flag)
#define SMEM_SCORE  32                     // float[128]
#define SMEM_SW     544                    // float[2][128]
#define SMEM_MB     1568                   // float[1]: M_bound
#define SMEM_BIASV  1600                   // float2[128]
#define SMEM_PACC   2624                   // float[2][128] producer partial combine
#define SMEM_A0     3648
#define SMEM_A1     (SMEM_A0 + TILE_BYTES) // 38464
#define SMEM_W      (SMEM_A1 + TILE_BYTES) // 73280
#define SMEM_TOTAL  (SMEM_W + TILE_BYTES)  // 108096

// Named barriers
#define BAR_PROD  1
#define BAR_CONS  2
#define BAR_FULL0 3
#define BAR_FULL1 4
#define BAR_DONE0 5
#define BAR_DONE1 6
#define BAR_SW0   7
#define BAR_SW1   8
#define BAR_ACC0  9
#define BAR_ACC1  10

#define BSYNC(id, n)   asm volatile("bar.sync %0, %1;"   :: "r"(id), "r"(n) : "memory")
#define BARRIVE(id, n) asm volatile("bar.arrive %0, %1;" :: "r"(id), "r"(n) : "memory")

// ============================================================
// Partial-result scratch + combine counters
// ============================================================
__device__ float g_pl[NCTA];
__device__ float g_pacc[NCTA * HID];
__device__ int   g_cnt[BB];   // zero-init; self-cleaning each launch

// ============================================================
// Helpers
// ============================================================
__device__ __forceinline__ uint32_t smem_to_u32(const void* p) {
    uint32_t a;
    asm("{ .reg .u64 t; cvta.to.shared.u64 t, %1; cvt.u32.u64 %0, t; }" : "=r"(a) : "l"(p));
    return a;
}

#define LDSM_X4(r, addr) \
    asm volatile("ldmatrix.sync.aligned.m8n8.x4.shared.b16 {%0,%1,%2,%3}, [%4];" \
        : "=r"((r)[0]), "=r"((r)[1]), "=r"((r)[2]), "=r"((r)[3]) : "r"(addr))

__device__ __forceinline__ void mma16816(float* c, const uint32_t* a, uint32_t b0, uint32_t b1) {
    asm volatile(
        "mma.sync.aligned.m16n8k16.row.col.f32.bf16.bf16.f32 "
        "{%0,%1,%2,%3}, {%4,%5,%6,%7}, {%8,%9}, {%0,%1,%2,%3};"
        : "+f"(c[0]), "+f"(c[1]), "+f"(c[2]), "+f"(c[3])
        : "r"(a[0]), "r"(a[1]), "r"(a[2]), "r"(a[3]), "r"(b0), "r"(b1));
}

__device__ __forceinline__ float bf_lo(uint32_t u) { return __uint_as_float(u << 16); }
__device__ __forceinline__ float bf_hi(uint32_t u) { return __uint_as_float(u & 0xffff0000u); }

__device__ __forceinline__ void cvt_sts(char* dst, int r, int lane, float4 v) {
    uint32_t p0, p1;
    asm("cvt.rn.bf16x2.f32 %0, %1, %2;" : "=r"(p0) : "f"(v.y), "f"(v.x));
    asm("cvt.rn.bf16x2.f32 %0, %1, %2;" : "=r"(p1) : "f"(v.w), "f"(v.z));
    *reinterpret_cast<uint2*>(dst + r * PITCH_B + lane * 8) = make_uint2(p0, p1);
}

// Full [128x128] tile load (W tile): 128 threads.
__device__ __forceinline__ void load_tile_bf16(const float4* __restrict__ src4,
                                               char* dst, int wid, int lane) {
#pragma unroll 16
    for (int it = 0; it < 32; ++it) {
        int r = it * 4 + wid;
        cvt_sts(dst, r, lane, __ldg(&src4[r * 32 + lane]));
    }
}

// Paired weighted accumulate: thread handles hid dims (2d, 2d+1) over 64 rows.
__device__ __forceinline__ float2 acc_tile2(const char* base, const float* w,
                                            int row0, float2 acc) {
    float a0x = 0.f, a0y = 0.f, a1x = 0.f, a1y = 0.f;
#pragma unroll
    for (int r = 0; r < 64; r += 2) {
        uint32_t u0 = *reinterpret_cast<const uint32_t*>(base + (row0 + r) * PITCH_B);
        uint32_t u1 = *reinterpret_cast<const uint32_t*>(base + (row0 + r + 1) * PITCH_B);
        const float w0 = w[row0 + r], w1 = w[row0 + r + 1];
        a0x = fmaf(w0, bf_lo(u0), a0x);  a0y = fmaf(w0, bf_hi(u0), a0y);
        a1x = fmaf(w1, bf_lo(u1), a1x);  a1y = fmaf(w1, bf_hi(u1), a1y);
    }
    return make_float2(acc.x + a0x + a1x, acc.y + a0y + a1y);
}

// ============================================================
// Main fused kernel (single launch; last CTA per batch combines)
// ============================================================
__global__ void __launch_bounds__(256, 2) attn_main_kernel(
    const float* __restrict__ hist, const float* __restrict__ cur,
    const float* __restrict__ Wx,   const float* __restrict__ Wxb,
    const float* __restrict__ Wh,   const float* __restrict__ Whb,
    const float* __restrict__ vw,   float* __restrict__ out)
{
    extern __shared__ __align__(16) char smem[];
    const int tid = threadIdx.x;
    const int cta = blockIdx.x, b = cta >> 3, c = cta & 7;
    const uint32_t sbase = smem_to_u32(smem);

    float* s_red   = reinterpret_cast<float*>(smem + SMEM_RED);
    float* s_score = reinterpret_cast<float*>(smem + SMEM_SCORE);
    float* s_w     = reinterpret_cast<float*>(smem + SMEM_SW);     // [2][128]
    float* s_mb    = reinterpret_cast<float*>(smem + SMEM_MB);
    float2* biasv  = reinterpret_cast<float2*>(smem + SMEM_BIASV);
    float* s_pacc  = reinterpret_cast<float*>(smem + SMEM_PACC);   // [2][128]
    char* bufA[2]  = { smem + SMEM_A0, smem + SMEM_A1 };

    const bool is_prod = (tid < 128);

    // ---------- init phase ----------
    if (is_prod) {
        const int wid = tid >> 5, lane = tid & 31;
        float* stage = reinterpret_cast<float*>(smem + SMEM_A0);
#pragma unroll 16
        for (int idx = tid; idx < ATTN * HID; idx += 128) {
            int a = idx >> 7, k = idx & 127;
            stage[k * 129 + a] = __ldg(&Wx[idx]);
        }
        BSYNC(BAR_PROD, 128);
        const float* cb = cur + b * HID;
        float s0 = 0.f, s1 = 0.f, s2 = 0.f, s3 = 0.f;
#pragma unroll
        for (int k = 0; k < HID; k += 4) {
            s0 = fmaf(stage[(k + 0) * 129 + tid], __ldg(&cb[k + 0]), s0);
            s1 = fmaf(stage[(k + 1) * 129 + tid], __ldg(&cb[k + 1]), s1);
            s2 = fmaf(stage[(k + 2) * 129 + tid], __ldg(&cb[k + 2]), s2);
            s3 = fmaf(stage[(k + 3) * 129 + tid], __ldg(&cb[k + 3]), s3);
        }
        const float vwi = __ldg(&vw[tid]);
        float s = Wxb[tid] + Whb[tid] + ((s0 + s1) + (s2 + s3));
        biasv[tid] = make_float2(s, vwi);
        // M_bound = sum_a |v_a|
        float av = fabsf(vwi);
#pragma unroll
        for (int o = 16; o; o >>= 1) av += __shfl_xor_sync(0xffffffffu, av, o);
        if (lane == 0) s_red[wid] = av;
        BSYNC(BAR_PROD, 128);
        if (tid == 0) s_mb[0] = (s_red[0] + s_red[1]) + (s_red[2] + s_red[3]);
    } else {
        const int ctid = tid - 128;
        load_tile_bf16(reinterpret_cast<const float4*>(Wh),
                       smem + SMEM_W, ctid >> 5, ctid & 31);
    }
    __syncthreads();
    const float M_bound = s_mb[0];

    const float4* histb = reinterpret_cast<const float4*>(
        hist + (size_t)b * S_TOTAL * HID);

    if (is_prod) {
        // ======================= PRODUCER =======================
        const int wid = tid >> 5, lane = tid & 31;
        const int half = tid >> 6;           // row half for paired accumulate
        const int row0 = half * 64;
        const int dpair = tid & 63;          // hid dims (2*dpair, 2*dpair+1)
        float2 facc2 = make_float2(0.f, 0.f);

        for (int i = 0; i < TILES_PER_CTA; ++i) {
            const int s = i & 1;
            const float4* src = histb + (size_t)(c + i * CPB) * TILE_S * 32;

            float4 pre[12];
#pragma unroll
            for (int k2 = 0; k2 < 12; ++k2)
                pre[k2] = __ldg(&src[(k2 * 4 + wid) * 32 + lane]);

            if (i >= 2) BSYNC(BAR_DONE0 + s, 256);

            char* dst = bufA[s];
#pragma unroll
            for (int k2 = 0; k2 < 12; ++k2)
                cvt_sts(dst, k2 * 4 + wid, lane, pre[k2]);
#pragma unroll 10
            for (int it = 12; it < 32; ++it) {
                int r = it * 4 + wid;
                cvt_sts(dst, r, lane, __ldg(&src[r * 32 + lane]));
            }
            BARRIVE(BAR_FULL0 + s, 256);

            if (i >= 1) {
                const int p = (i - 1) & 1;
                BSYNC(BAR_SW0 + p, 256);
                facc2 = acc_tile2(bufA[p] + dpair * 4, s_w + p * 128, row0, facc2);
                BARRIVE(BAR_ACC0 + p, 256);
            }
        }
        {
            const int p = (TILES_PER_CTA - 1) & 1;
            BSYNC(BAR_SW0 + p, 256);
            facc2 = acc_tile2(bufA[p] + dpair * 4, s_w + p * 128, row0, facc2);
        }
        // cross-half combine
        s_pacc[half * 128 + dpair * 2 + 0] = facc2.x;
        s_pacc[half * 128 + dpair * 2 + 1] = facc2.y;
        BSYNC(BAR_PROD, 128);
        g_pacc[cta * HID + tid] = s_pacc[tid] + s_pacc[128 + tid];
    } else {
        // ======================= CONSUMER =======================
        const int ctid = tid - 128;
        const int cw = ctid >> 5, lane = ctid & 31;
        const uint32_t sW = sbase + SMEM_W;

        const int g8 = lane & 7;
        const uint32_t rowA_off = (uint32_t)((((lane >> 3) & 1) * 8 + g8) * PITCH_B + (lane >> 4) * 16);
        const uint32_t rowB_off = (uint32_t)(((lane >> 4) * 8 + g8) * PITCH_B + ((lane >> 3) & 1) * 16);

        float l_run = 0.f;

        for (int i = 0; i < TILES_PER_CTA; ++i) {
            const int s = i & 1;
            BSYNC(BAR_FULL0 + s, 256);
            const uint32_t sA = sbase + (s ? SMEM_A1 : SMEM_A0);

            // ---- load ALL A fragments once (held in regs) ----
            uint32_t afr[2][8][4];
#pragma unroll
            for (int mt = 0; mt < 2; ++mt)
#pragma unroll
                for (int k = 0; k < 8; ++k)
                    LDSM_X4(afr[mt][k], sA + (uint32_t)((cw * 32 + mt * 16) * PITCH_B + k * 32) + rowA_off);
            BARRIVE(BAR_DONE0 + s, 256);   // buf s free NOW (A lives in regs)

            // ---- sweep B in 16-col chunks ----
            float sp[2][2] = {{0.f, 0.f}, {0.f, 0.f}};
#pragma unroll
            for (int nc = 0; nc < 8; ++nc) {
                float acc[2][2][4];
#pragma unroll
                for (int mt = 0; mt < 2; ++mt)
#pragma unroll
                    for (int nt = 0; nt < 2; ++nt)
#pragma unroll
                        for (int r = 0; r < 4; ++r) acc[mt][nt][r] = 0.f;
#pragma unroll
                for (int k = 0; k < 8; ++k) {
                    uint32_t bfr[4];
                    LDSM_X4(bfr, sW + (uint32_t)((nc * 16) * PITCH_B + k * 32) + rowB_off);
#pragma unroll
                    for (int mt = 0; mt < 2; ++mt) {
                        mma16816(acc[mt][0], afr[mt][k], bfr[0], bfr[1]);
                        mma16816(acc[mt][1], afr[mt][k], bfr[2], bfr[3]);
                    }
                }
#pragma unroll
                for (int mt = 0; mt < 2; ++mt)
#pragma unroll
                    for (int nt = 0; nt < 2; ++nt) {
                        const int colb = nc * 16 + nt * 8 + 2 * (lane & 3);
                        const float2 bv0 = biasv[colb];
                        const float2 bv1 = biasv[colb + 1];
#pragma unroll
                        for (int rr = 0; rr < 2; ++rr) {
                            float x0 = acc[mt][nt][rr * 2 + 0] + bv0.x;
                            float x1 = acc[mt][nt][rr * 2 + 1] + bv1.x;
                            float t0, t1;
                            asm("tanh.approx.f32 %0, %1;" : "=f"(t0) : "f"(x0));
                            asm("tanh.approx.f32 %0, %1;" : "=f"(t1) : "f"(x1));
                            sp[mt][rr] = fmaf(t0, bv0.y, sp[mt][rr]);
                            sp[mt][rr] = fmaf(t1, bv1.y, sp[mt][rr]);
                        }
                    }
            }

            // ---- scores -> smem (warp-local scatter) ----
#pragma unroll
            for (int mt = 0; mt < 2; ++mt)
#pragma unroll
                for (int rr = 0; rr < 2; ++rr) {
                    float v = sp[mt][rr];
                    v += __shfl_xor_sync(0xffffffffu, v, 1);
                    v += __shfl_xor_sync(0xffffffffu, v, 2);
                    if ((lane & 3) == 0)
                        s_score[cw * 32 + mt * 16 + rr * 8 + (lane >> 2)] = v;
                }
            __syncwarp();

            // ---- static-max softmax ----
            const float p = __expf(s_score[ctid] - M_bound);

            if (i >= 2) BSYNC(BAR_ACC0 + s, 256);
            s_w[s * 128 + ctid] = p;

            float ps = p;
#pragma unroll
            for (int o = 16; o; o >>= 1) ps += __shfl_xor_sync(0xffffffffu, ps, o);
            if (lane == 0) s_red[4 + cw] = ps;
            BSYNC(BAR_CONS, 128);
            l_run += (s_red[4] + s_red[5]) + (s_red[6] + s_red[7]);
            BARRIVE(BAR_SW0 + s, 256);
        }
        if (ctid == 0) g_pl[cta] = l_run;
    }

    // ---------- last-CTA-per-batch combine ----------
    __threadfence();
    __syncthreads();
    int* s_flag = reinterpret_cast<int*>(smem + SMEM_RED);
    if (tid == 0) {
        int old = atomicAdd(&g_cnt[b], 1);
        s_flag[0] = (old == CPB - 1) ? 1 : 0;
    }
    __syncthreads();
    if (s_flag[0]) {
        __threadfence();
        if (tid < HID) {
            float L = 0.f, num = 0.f;
#pragma unroll
            for (int j = 0; j < CPB; ++j) {
                L   += __ldcg(&g_pl[b * CPB + j]);
                num += __ldcg(&g_pacc[(b * CPB + j) * HID + tid]);
            }
            out[b * HID + tid] = cur[b * HID + tid] + num / L;
        }
        if (tid == 0) g_cnt[b] = 0;
    }
}

// ============================================================
// Launch
// ============================================================
extern "C" void kernel_launch(void* const* d_in, const int* in_sizes, int n_in,
                              void* d_out, int out_size)
{
    (void)in_sizes; (void)n_in; (void)out_size;
    const float* cur  = (const float*)d_in[0];
    const float* hist = (const float*)d_in[1];
    const float* Wx   = (const float*)d_in[2];
    const float* Wxb  = (const float*)d_in[3];
    const float* Wh   = (const float*)d_in[4];
    const float* Whb  = (const float*)d_in[5];
    const float* vw   = (const float*)d_in[6];
    float* out = (float*)d_out;

    cudaFuncSetAttribute(attn_main_kernel,
                         cudaFuncAttributeMaxDynamicSharedMemorySize, SMEM_TOTAL);

    attn_main_kernel<<<NCTA, 256, SMEM_TOTAL>>>(hist, cur, Wx, Wxb, Wh, Whb, vw, out);
}

// round 9
// speedup vs baseline: 1.0369x; 1.0369x over previous
#include <cuda_runtime.h>
#include <cuda_bf16.h>
#include <cstdint>

// ============================================================
// Problem constants
// ============================================================
#define BB    32
#define HID   128
#define ATTN  128
#define S_TOTAL   8192
#define TILE_S    128
#define TILES_PB  (S_TOTAL / TILE_S) // 64 tiles per batch
#define NCTA  296                    // 8 batches x10 CTAs + 24 batches x9 CTAs

// bf16 tile [128 rows][128 cols] with 16B row pad
#define PITCH_H   136
#define PITCH_B   (PITCH_H * 2)      // 272
#define TILE_BYTES (128 * PITCH_B)   // 34816

// SMEM layout (bytes)
#define SMEM_RED    0                      // float[8] (+ combine flag)
#define SMEM_SCORE  32                     // float[128]
#define SMEM_SW     544                    // float[2][128]
#define SMEM_MB     1568                   // float[1]: M_bound
#define SMEM_BIASV  1600                   // float2[128]
#define SMEM_PACC   2624                   // float[2][128] producer partial combine
#define SMEM_A0     3648
#define SMEM_A1     (SMEM_A0 + TILE_BYTES) // 38464
#define SMEM_W      (SMEM_A1 + TILE_BYTES) // 73280
#define SMEM_TOTAL  (SMEM_W + TILE_BYTES)  // 108096

// Named barriers
#define BAR_PROD  1
#define BAR_CONS  2
#define BAR_FULL0 3
#define BAR_FULL1 4
#define BAR_DONE0 5
#define BAR_DONE1 6
#define BAR_SW0   7
#define BAR_SW1   8
#define BAR_ACC0  9
#define BAR_ACC1  10

#define BSYNC(id, n)   asm volatile("bar.sync %0, %1;"   :: "r"(id), "r"(n) : "memory")
#define BARRIVE(id, n) asm volatile("bar.arrive %0, %1;" :: "r"(id), "r"(n) : "memory")

// ============================================================
// Partial-result scratch + combine counters
// ============================================================
__device__ float g_pl[NCTA];
__device__ float g_pacc[NCTA * HID];
__device__ int   g_cnt[BB];   // zero-init; self-cleaning each launch

// ============================================================
// Helpers
// ============================================================
__device__ __forceinline__ uint32_t smem_to_u32(const void* p) {
    uint32_t a;
    asm("{ .reg .u64 t; cvta.to.shared.u64 t, %1; cvt.u32.u64 %0, t; }" : "=r"(a) : "l"(p));
    return a;
}

#define LDSM_X4(r, addr) \
    asm volatile("ldmatrix.sync.aligned.m8n8.x4.shared.b16 {%0,%1,%2,%3}, [%4];" \
        : "=r"((r)[0]), "=r"((r)[1]), "=r"((r)[2]), "=r"((r)[3]) : "r"(addr))

__device__ __forceinline__ void mma16816(float* c, const uint32_t* a, uint32_t b0, uint32_t b1) {
    asm volatile(
        "mma.sync.aligned.m16n8k16.row.col.f32.bf16.bf16.f32 "
        "{%0,%1,%2,%3}, {%4,%5,%6,%7}, {%8,%9}, {%0,%1,%2,%3};"
        : "+f"(c[0]), "+f"(c[1]), "+f"(c[2]), "+f"(c[3])
        : "r"(a[0]), "r"(a[1]), "r"(a[2]), "r"(a[3]), "r"(b0), "r"(b1));
}

__device__ __forceinline__ float bf_lo(uint32_t u) { return __uint_as_float(u << 16); }
__device__ __forceinline__ float bf_hi(uint32_t u) { return __uint_as_float(u & 0xffff0000u); }

__device__ __forceinline__ void cvt_sts(char* dst, int r, int lane, float4 v) {
    uint32_t p0, p1;
    asm("cvt.rn.bf16x2.f32 %0, %1, %2;" : "=r"(p0) : "f"(v.y), "f"(v.x));
    asm("cvt.rn.bf16x2.f32 %0, %1, %2;" : "=r"(p1) : "f"(v.w), "f"(v.z));
    *reinterpret_cast<uint2*>(dst + r * PITCH_B + lane * 8) = make_uint2(p0, p1);
}

// Full [128x128] tile load (W tile): 128 threads.
__device__ __forceinline__ void load_tile_bf16(const float4* __restrict__ src4,
                                               char* dst, int wid, int lane) {
#pragma unroll 16
    for (int it = 0; it < 32; ++it) {
        int r = it * 4 + wid;
        cvt_sts(dst, r, lane, __ldg(&src4[r * 32 + lane]));
    }
}

// Paired weighted accumulate: thread handles hid dims (2d, 2d+1) over 64 rows.
__device__ __forceinline__ float2 acc_tile2(const char* base, const float* w,
                                            int row0, float2 acc) {
    float a0x = 0.f, a0y = 0.f, a1x = 0.f, a1y = 0.f;
#pragma unroll
    for (int r = 0; r < 64; r += 2) {
        uint32_t u0 = *reinterpret_cast<const uint32_t*>(base + (row0 + r) * PITCH_B);
        uint32_t u1 = *reinterpret_cast<const uint32_t*>(base + (row0 + r + 1) * PITCH_B);
        const float w0 = w[row0 + r], w1 = w[row0 + r + 1];
        a0x = fmaf(w0, bf_lo(u0), a0x);  a0y = fmaf(w0, bf_hi(u0), a0y);
        a1x = fmaf(w1, bf_lo(u1), a1x);  a1y = fmaf(w1, bf_hi(u1), a1y);
    }
    return make_float2(acc.x + a0x + a1x, acc.y + a0y + a1y);
}

// ============================================================
// Main fused kernel (single launch; last CTA per batch combines)
// ============================================================
__global__ void __launch_bounds__(256, 2) attn_main_kernel(
    const float* __restrict__ hist, const float* __restrict__ cur,
    const float* __restrict__ Wx,   const float* __restrict__ Wxb,
    const float* __restrict__ Wh,   const float* __restrict__ Whb,
    const float* __restrict__ vw,   float* __restrict__ out)
{
    extern __shared__ __align__(16) char smem[];
    const int tid = threadIdx.x;
    const int cta = blockIdx.x;

    // ---- balanced CTA -> (batch, tile range) mapping ----
    // batches 0..7: 10 CTAs; batches 8..31: 9 CTAs  (total 296)
    int b, c, cpb, base;
    if (cta < 80) { b = cta / 10; c = cta - b * 10; cpb = 10; base = b * 10; }
    else { int x = cta - 80; b = 8 + x / 9; c = x - (b - 8) * 9; cpb = 9; base = 80 + (b - 8) * 9; }
    const int q = TILES_PB / cpb, r = TILES_PB % cpb;
    const int tcount = q + (c < r ? 1 : 0);
    const int tstart = c * q + (c < r ? c : r);

    const uint32_t sbase = smem_to_u32(smem);
    float* s_red   = reinterpret_cast<float*>(smem + SMEM_RED);
    float* s_score = reinterpret_cast<float*>(smem + SMEM_SCORE);
    float* s_w     = reinterpret_cast<float*>(smem + SMEM_SW);     // [2][128]
    float* s_mb    = reinterpret_cast<float*>(smem + SMEM_MB);
    float2* biasv  = reinterpret_cast<float2*>(smem + SMEM_BIASV);
    float* s_pacc  = reinterpret_cast<float*>(smem + SMEM_PACC);   // [2][128]
    char* bufA[2]  = { smem + SMEM_A0, smem + SMEM_A1 };

    const bool is_prod = (tid < 128);

    // ---------- init phase ----------
    if (is_prod) {
        const int wid = tid >> 5, lane = tid & 31;
        float* stage = reinterpret_cast<float*>(smem + SMEM_A0);
#pragma unroll 16
        for (int idx = tid; idx < ATTN * HID; idx += 128) {
            int a = idx >> 7, k = idx & 127;
            stage[k * 129 + a] = __ldg(&Wx[idx]);
        }
        BSYNC(BAR_PROD, 128);
        const float* cb = cur + b * HID;
        float s0 = 0.f, s1 = 0.f, s2 = 0.f, s3 = 0.f;
#pragma unroll
        for (int k = 0; k < HID; k += 4) {
            s0 = fmaf(stage[(k + 0) * 129 + tid], __ldg(&cb[k + 0]), s0);
            s1 = fmaf(stage[(k + 1) * 129 + tid], __ldg(&cb[k + 1]), s1);
            s2 = fmaf(stage[(k + 2) * 129 + tid], __ldg(&cb[k + 2]), s2);
            s3 = fmaf(stage[(k + 3) * 129 + tid], __ldg(&cb[k + 3]), s3);
        }
        const float vwi = __ldg(&vw[tid]);
        float s = Wxb[tid] + Whb[tid] + ((s0 + s1) + (s2 + s3));
        biasv[tid] = make_float2(s, vwi);
        // M_bound = sum_a |v_a|
        float av = fabsf(vwi);
#pragma unroll
        for (int o = 16; o; o >>= 1) av += __shfl_xor_sync(0xffffffffu, av, o);
        if (lane == 0) s_red[wid] = av;
        BSYNC(BAR_PROD, 128);
        if (tid == 0) s_mb[0] = (s_red[0] + s_red[1]) + (s_red[2] + s_red[3]);
    } else {
        const int ctid = tid - 128;
        load_tile_bf16(reinterpret_cast<const float4*>(Wh),
                       smem + SMEM_W, ctid >> 5, ctid & 31);
    }
    __syncthreads();
    const float M_bound = s_mb[0];

    const float4* histb = reinterpret_cast<const float4*>(
        hist + (size_t)b * S_TOTAL * HID);

    if (is_prod) {
        // ======================= PRODUCER =======================
        const int wid = tid >> 5, lane = tid & 31;
        const int half = tid >> 6;
        const int row0 = half * 64;
        const int dpair = tid & 63;
        float2 facc2 = make_float2(0.f, 0.f);

        for (int i = 0; i < tcount; ++i) {
            const int s = i & 1;
            const float4* src = histb + (size_t)(tstart + i) * TILE_S * 32;

            float4 pre[12];
#pragma unroll
            for (int k2 = 0; k2 < 12; ++k2)
                pre[k2] = __ldg(&src[(k2 * 4 + wid) * 32 + lane]);

            if (i >= 2) BSYNC(BAR_DONE0 + s, 256);

            char* dst = bufA[s];
#pragma unroll
            for (int k2 = 0; k2 < 12; ++k2)
                cvt_sts(dst, k2 * 4 + wid, lane, pre[k2]);
#pragma unroll 10
            for (int it = 12; it < 32; ++it) {
                int rr = it * 4 + wid;
                cvt_sts(dst, rr, lane, __ldg(&src[rr * 32 + lane]));
            }
            BARRIVE(BAR_FULL0 + s, 256);

            if (i >= 1) {
                const int p = (i - 1) & 1;
                BSYNC(BAR_SW0 + p, 256);
                facc2 = acc_tile2(bufA[p] + dpair * 4, s_w + p * 128, row0, facc2);
                BARRIVE(BAR_ACC0 + p, 256);
            }
        }
        {
            const int p = (tcount - 1) & 1;
            BSYNC(BAR_SW0 + p, 256);
            facc2 = acc_tile2(bufA[p] + dpair * 4, s_w + p * 128, row0, facc2);
        }
        // cross-half combine
        s_pacc[half * 128 + dpair * 2 + 0] = facc2.x;
        s_pacc[half * 128 + dpair * 2 + 1] = facc2.y;
        BSYNC(BAR_PROD, 128);
        g_pacc[cta * HID + tid] = s_pacc[tid] + s_pacc[128 + tid];
    } else {
        // ======================= CONSUMER =======================
        const int ctid = tid - 128;
        const int cw = ctid >> 5, lane = ctid & 31;
        const uint32_t sW = sbase + SMEM_W;

        const int g8 = lane & 7;
        const uint32_t rowA_off = (uint32_t)((((lane >> 3) & 1) * 8 + g8) * PITCH_B + (lane >> 4) * 16);
        const uint32_t rowB_off = (uint32_t)(((lane >> 4) * 8 + g8) * PITCH_B + ((lane >> 3) & 1) * 16);

        float l_run = 0.f;

        for (int i = 0; i < tcount; ++i) {
            const int s = i & 1;
            BSYNC(BAR_FULL0 + s, 256);
            const uint32_t sA = sbase + (s ? SMEM_A1 : SMEM_A0);

            // ---- load ALL A fragments once (held in regs) ----
            uint32_t afr[2][8][4];
#pragma unroll
            for (int mt = 0; mt < 2; ++mt)
#pragma unroll
                for (int k = 0; k < 8; ++k)
                    LDSM_X4(afr[mt][k], sA + (uint32_t)((cw * 32 + mt * 16) * PITCH_B + k * 32) + rowA_off);
            BARRIVE(BAR_DONE0 + s, 256);   // buf s free NOW (A lives in regs)

            // ---- sweep B in 16-col chunks ----
            float sp[2][2] = {{0.f, 0.f}, {0.f, 0.f}};
#pragma unroll
            for (int nc = 0; nc < 8; ++nc) {
                float acc[2][2][4];
#pragma unroll
                for (int mt = 0; mt < 2; ++mt)
#pragma unroll
                    for (int nt = 0; nt < 2; ++nt)
#pragma unroll
                        for (int rr = 0; rr < 4; ++rr) acc[mt][nt][rr] = 0.f;
#pragma unroll
                for (int k = 0; k < 8; ++k) {
                    uint32_t bfr[4];
                    LDSM_X4(bfr, sW + (uint32_t)((nc * 16) * PITCH_B + k * 32) + rowB_off);
#pragma unroll
                    for (int mt = 0; mt < 2; ++mt) {
                        mma16816(acc[mt][0], afr[mt][k], bfr[0], bfr[1]);
                        mma16816(acc[mt][1], afr[mt][k], bfr[2], bfr[3]);
                    }
                }
#pragma unroll
                for (int mt = 0; mt < 2; ++mt)
#pragma unroll
                    for (int nt = 0; nt < 2; ++nt) {
                        const int colb = nc * 16 + nt * 8 + 2 * (lane & 3);
                        const float2 bv0 = biasv[colb];
                        const float2 bv1 = biasv[colb + 1];
#pragma unroll
                        for (int rr = 0; rr < 2; ++rr) {
                            float x0 = acc[mt][nt][rr * 2 + 0] + bv0.x;
                            float x1 = acc[mt][nt][rr * 2 + 1] + bv1.x;
                            float t0, t1;
                            asm("tanh.approx.f32 %0, %1;" : "=f"(t0) : "f"(x0));
                            asm("tanh.approx.f32 %0, %1;" : "=f"(t1) : "f"(x1));
                            sp[mt][rr] = fmaf(t0, bv0.y, sp[mt][rr]);
                            sp[mt][rr] = fmaf(t1, bv1.y, sp[mt][rr]);
                        }
                    }
            }

            // ---- scores -> smem (warp-local scatter) ----
#pragma unroll
            for (int mt = 0; mt < 2; ++mt)
#pragma unroll
                for (int rr = 0; rr < 2; ++rr) {
                    float v = sp[mt][rr];
                    v += __shfl_xor_sync(0xffffffffu, v, 1);
                    v += __shfl_xor_sync(0xffffffffu, v, 2);
                    if ((lane & 3) == 0)
                        s_score[cw * 32 + mt * 16 + rr * 8 + (lane >> 2)] = v;
                }
            __syncwarp();

            // ---- static-max softmax ----
            const float p = __expf(s_score[ctid] - M_bound);

            if (i >= 2) BSYNC(BAR_ACC0 + s, 256);
            s_w[s * 128 + ctid] = p;

            float ps = p;
#pragma unroll
            for (int o = 16; o; o >>= 1) ps += __shfl_xor_sync(0xffffffffu, ps, o);
            if (lane == 0) s_red[4 + cw] = ps;
            BSYNC(BAR_CONS, 128);
            l_run += (s_red[4] + s_red[5]) + (s_red[6] + s_red[7]);
            BARRIVE(BAR_SW0 + s, 256);
        }
        if (ctid == 0) g_pl[cta] = l_run;
    }

    // ---------- last-CTA-per-batch combine ----------
    __threadfence();
    __syncthreads();
    int* s_flag = reinterpret_cast<int*>(smem + SMEM_RED);
    if (tid == 0) {
        int old = atomicAdd(&g_cnt[b], 1);
        s_flag[0] = (old == cpb - 1) ? 1 : 0;
    }
    __syncthreads();
    if (s_flag[0]) {
        __threadfence();
        if (tid < HID) {
            float L = 0.f, num = 0.f;
            for (int j = 0; j < cpb; ++j) {
                L   += __ldcg(&g_pl[base + j]);
                num += __ldcg(&g_pacc[(base + j) * HID + tid]);
            }
            out[b * HID + tid] = cur[b * HID + tid] + num / L;
        }
        if (tid == 0) g_cnt[b] = 0;   // reset for next graph replay
    }
}

// ============================================================
// Launch
// ============================================================
extern "C" void kernel_launch(void* const* d_in, const int* in_sizes, int n_in,
                              void* d_out, int out_size)
{
    (void)in_sizes; (void)n_in; (void)out_size;
    const float* cur  = (const float*)d_in[0];
    const float* hist = (const float*)d_in[1];
    const float* Wx   = (const float*)d_in[2];
    const float* Wxb  = (const float*)d_in[3];
    const float* Wh   = (const float*)d_in[4];
    const float* Whb  = (const float*)d_in[5];
    const float* vw   = (const float*)d_in[6];
    float* out = (float*)d_out;

    cudaFuncSetAttribute(attn_main_kernel,
                         cudaFuncAttributeMaxDynamicSharedMemorySize, SMEM_TOTAL);

    attn_main_kernel<<<NCTA, 256, SMEM_TOTAL>>>(hist, cur, Wx, Wxb, Wh, Whb, vw, out);
}

// round 10
// speedup vs baseline: 1.0697x; 1.0317x over previous
#include <cuda_runtime.h>
#include <cuda_bf16.h>
#include <cstdint>

// ============================================================
// Problem constants
// ============================================================
#define BB    32
#define HID   128
#define ATTN  128
#define S_TOTAL   8192
#define TILE_S    128
#define TILES_PB  (S_TOTAL / TILE_S) // 64 tiles per batch
#define NCTA  296                    // 8 batches x10 CTAs + 24 batches x9 CTAs

// bf16 tile [128 rows][128 cols] with 16B row pad
#define PITCH_H   136
#define PITCH_B   (PITCH_H * 2)      // 272
#define TILE_BYTES (128 * PITCH_B)   // 34816

// SMEM layout (bytes)
#define SMEM_RED    0                      // float[8] (+ combine flag)
#define SMEM_SCORE  32                     // float[128]
#define SMEM_SW     544                    // float[4][128]  (4-slot ring)
#define SMEM_MB     2592                   // float[1]: M_bound
#define SMEM_BIASV  2624                   // float2[128]
#define SMEM_PACC   3648                   // float[2][128] producer partial combine
#define SMEM_A0     4672
#define SMEM_A1     (SMEM_A0 + TILE_BYTES) // 39488
#define SMEM_W      (SMEM_A1 + TILE_BYTES) // 74304
#define SMEM_TOTAL  (SMEM_W + TILE_BYTES)  // 109120

// Named barriers
#define BAR_PROD  1
#define BAR_CONS  2
#define BAR_FULL0 3   // +s (2)
#define BAR_DONE0 5   // +s (2)
#define BAR_SW0   7   // +slot (4): 7,8,9,10

#define BSYNC(id, n)   asm volatile("bar.sync %0, %1;"   :: "r"(id), "r"(n) : "memory")
#define BARRIVE(id, n) asm volatile("bar.arrive %0, %1;" :: "r"(id), "r"(n) : "memory")

// ============================================================
// Partial-result scratch + combine counters
// ============================================================
__device__ float g_pl[NCTA];
__device__ float g_pacc[NCTA * HID];
__device__ int   g_cnt[BB];   // zero-init; self-cleaning each launch

// ============================================================
// Helpers
// ============================================================
__device__ __forceinline__ uint32_t smem_to_u32(const void* p) {
    uint32_t a;
    asm("{ .reg .u64 t; cvta.to.shared.u64 t, %1; cvt.u32.u64 %0, t; }" : "=r"(a) : "l"(p));
    return a;
}

#define LDSM_X4(r, addr) \
    asm volatile("ldmatrix.sync.aligned.m8n8.x4.shared.b16 {%0,%1,%2,%3}, [%4];" \
        : "=r"((r)[0]), "=r"((r)[1]), "=r"((r)[2]), "=r"((r)[3]) : "r"(addr))

__device__ __forceinline__ void mma16816(float* c, const uint32_t* a, uint32_t b0, uint32_t b1) {
    asm volatile(
        "mma.sync.aligned.m16n8k16.row.col.f32.bf16.bf16.f32 "
        "{%0,%1,%2,%3}, {%4,%5,%6,%7}, {%8,%9}, {%0,%1,%2,%3};"
        : "+f"(c[0]), "+f"(c[1]), "+f"(c[2]), "+f"(c[3])
        : "r"(a[0]), "r"(a[1]), "r"(a[2]), "r"(a[3]), "r"(b0), "r"(b1));
}

__device__ __forceinline__ float bf_lo(uint32_t u) { return __uint_as_float(u << 16); }
__device__ __forceinline__ float bf_hi(uint32_t u) { return __uint_as_float(u & 0xffff0000u); }

__device__ __forceinline__ void cvt_sts(char* dst, int r, int lane, float4 v) {
    uint32_t p0, p1;
    asm("cvt.rn.bf16x2.f32 %0, %1, %2;" : "=r"(p0) : "f"(v.y), "f"(v.x));
    asm("cvt.rn.bf16x2.f32 %0, %1, %2;" : "=r"(p1) : "f"(v.w), "f"(v.z));
    *reinterpret_cast<uint2*>(dst + r * PITCH_B + lane * 8) = make_uint2(p0, p1);
}

// Full [128x128] tile load (W tile): 128 threads.
__device__ __forceinline__ void load_tile_bf16(const float4* __restrict__ src4,
                                               char* dst, int wid, int lane) {
#pragma unroll 16
    for (int it = 0; it < 32; ++it) {
        int r = it * 4 + wid;
        cvt_sts(dst, r, lane, __ldg(&src4[r * 32 + lane]));
    }
}

// Paired weighted accumulate: thread handles hid dims (2d, 2d+1) over 64 rows.
__device__ __forceinline__ float2 acc_tile2(const char* base, const float* w,
                                            int row0, float2 acc) {
    float a0x = 0.f, a0y = 0.f, a1x = 0.f, a1y = 0.f;
#pragma unroll
    for (int r = 0; r < 64; r += 2) {
        uint32_t u0 = *reinterpret_cast<const uint32_t*>(base + (row0 + r) * PITCH_B);
        uint32_t u1 = *reinterpret_cast<const uint32_t*>(base + (row0 + r + 1) * PITCH_B);
        const float w0 = w[row0 + r], w1 = w[row0 + r + 1];
        a0x = fmaf(w0, bf_lo(u0), a0x);  a0y = fmaf(w0, bf_hi(u0), a0y);
        a1x = fmaf(w1, bf_lo(u1), a1x);  a1y = fmaf(w1, bf_hi(u1), a1y);
    }
    return make_float2(acc.x + a0x + a1x, acc.y + a0y + a1y);
}

// ============================================================
// Main fused kernel (single launch; last CTA per batch combines)
// ============================================================
__global__ void __launch_bounds__(256, 2) attn_main_kernel(
    const float* __restrict__ hist, const float* __restrict__ cur,
    const float* __restrict__ Wx,   const float* __restrict__ Wxb,
    const float* __restrict__ Wh,   const float* __restrict__ Whb,
    const float* __restrict__ vw,   float* __restrict__ out)
{
    extern __shared__ __align__(16) char smem[];
    const int tid = threadIdx.x;
    const int cta = blockIdx.x;

    // ---- balanced CTA -> (batch, tile range) mapping ----
    int b, c, cpb, base;
    if (cta < 80) { b = cta / 10; c = cta - b * 10; cpb = 10; base = b * 10; }
    else { int x = cta - 80; b = 8 + x / 9; c = x - (b - 8) * 9; cpb = 9; base = 80 + (b - 8) * 9; }
    const int q = TILES_PB / cpb, r = TILES_PB % cpb;
    const int tcount = q + (c < r ? 1 : 0);
    const int tstart = c * q + (c < r ? c : r);

    const uint32_t sbase = smem_to_u32(smem);
    float* s_red   = reinterpret_cast<float*>(smem + SMEM_RED);
    float* s_score = reinterpret_cast<float*>(smem + SMEM_SCORE);
    float* s_w     = reinterpret_cast<float*>(smem + SMEM_SW);     // [4][128]
    float* s_mb    = reinterpret_cast<float*>(smem + SMEM_MB);
    float2* biasv  = reinterpret_cast<float2*>(smem + SMEM_BIASV);
    float* s_pacc  = reinterpret_cast<float*>(smem + SMEM_PACC);   // [2][128]
    char* bufA[2]  = { smem + SMEM_A0, smem + SMEM_A1 };

    const bool is_prod = (tid < 128);

    // ---------- init phase ----------
    if (is_prod) {
        const int wid = tid >> 5, lane = tid & 31;
        float* stage = reinterpret_cast<float*>(smem + SMEM_A0);
#pragma unroll 16
        for (int idx = tid; idx < ATTN * HID; idx += 128) {
            int a = idx >> 7, k = idx & 127;
            stage[k * 129 + a] = __ldg(&Wx[idx]);
        }
        BSYNC(BAR_PROD, 128);
        const float* cb = cur + b * HID;
        float s0 = 0.f, s1 = 0.f, s2 = 0.f, s3 = 0.f;
#pragma unroll
        for (int k = 0; k < HID; k += 4) {
            s0 = fmaf(stage[(k + 0) * 129 + tid], __ldg(&cb[k + 0]), s0);
            s1 = fmaf(stage[(k + 1) * 129 + tid], __ldg(&cb[k + 1]), s1);
            s2 = fmaf(stage[(k + 2) * 129 + tid], __ldg(&cb[k + 2]), s2);
            s3 = fmaf(stage[(k + 3) * 129 + tid], __ldg(&cb[k + 3]), s3);
        }
        const float vwi = __ldg(&vw[tid]);
        float s = Wxb[tid] + Whb[tid] + ((s0 + s1) + (s2 + s3));
        biasv[tid] = make_float2(s, vwi);
        // M_bound = sum_a |v_a|
        float av = fabsf(vwi);
#pragma unroll
        for (int o = 16; o; o >>= 1) av += __shfl_xor_sync(0xffffffffu, av, o);
        if (lane == 0) s_red[wid] = av;
        BSYNC(BAR_PROD, 128);
        if (tid == 0) s_mb[0] = (s_red[0] + s_red[1]) + (s_red[2] + s_red[3]);
    } else {
        const int ctid = tid - 128;
        load_tile_bf16(reinterpret_cast<const float4*>(Wh),
                       smem + SMEM_W, ctid >> 5, ctid & 31);
    }
    __syncthreads();
    const float M_bound = s_mb[0];

    const float4* histb = reinterpret_cast<const float4*>(
        hist + (size_t)b * S_TOTAL * HID);

    if (is_prod) {
        // ======================= PRODUCER =======================
        const int wid = tid >> 5, lane = tid & 31;
        const int half = tid >> 6;
        const int row0 = half * 64;
        const int dpair = tid & 63;
        float2 facc2 = make_float2(0.f, 0.f);

        // prologue: prefetch first 12 rows of tile 0
        float4 pre[12];
        {
            const float4* src0 = histb + (size_t)tstart * TILE_S * 32;
#pragma unroll
            for (int k2 = 0; k2 < 12; ++k2)
                pre[k2] = __ldg(&src0[(k2 * 4 + wid) * 32 + lane]);
        }

        for (int i = 0; i < tcount; ++i) {
            const int s = i & 1;
            const float4* src = histb + (size_t)(tstart + i) * TILE_S * 32;

            if (i >= 2) BSYNC(BAR_DONE0 + s, 256);

            char* dst = bufA[s];
#pragma unroll
            for (int k2 = 0; k2 < 12; ++k2)
                cvt_sts(dst, k2 * 4 + wid, lane, pre[k2]);
#pragma unroll 10
            for (int it = 12; it < 32; ++it) {
                int rr = it * 4 + wid;
                cvt_sts(dst, rr, lane, __ldg(&src[rr * 32 + lane]));
            }
            BARRIVE(BAR_FULL0 + s, 256);

            // prefetch NEXT tile now: LDGs fly during SW wait + accumulate
            if (i + 1 < tcount) {
                const float4* srcn = histb + (size_t)(tstart + i + 1) * TILE_S * 32;
#pragma unroll
                for (int k2 = 0; k2 < 12; ++k2)
                    pre[k2] = __ldg(&srcn[(k2 * 4 + wid) * 32 + lane]);
            }

            if (i >= 1) {
                const int p = i - 1;
                BSYNC(BAR_SW0 + (p & 3), 256);
                facc2 = acc_tile2(bufA[p & 1] + dpair * 4, s_w + (p & 3) * 128, row0, facc2);
            }
        }
        {
            const int p = tcount - 1;
            BSYNC(BAR_SW0 + (p & 3), 256);
            facc2 = acc_tile2(bufA[p & 1] + dpair * 4, s_w + (p & 3) * 128, row0, facc2);
        }
        // cross-half combine
        s_pacc[half * 128 + dpair * 2 + 0] = facc2.x;
        s_pacc[half * 128 + dpair * 2 + 1] = facc2.y;
        BSYNC(BAR_PROD, 128);
        g_pacc[cta * HID + tid] = s_pacc[tid] + s_pacc[128 + tid];
    } else {
        // ======================= CONSUMER =======================
        const int ctid = tid - 128;
        const int cw = ctid >> 5, lane = ctid & 31;
        const uint32_t sW = sbase + SMEM_W;

        const int g8 = lane & 7;
        const uint32_t rowA_off = (uint32_t)((((lane >> 3) & 1) * 8 + g8) * PITCH_B + (lane >> 4) * 16);
        const uint32_t rowB_off = (uint32_t)(((lane >> 4) * 8 + g8) * PITCH_B + ((lane >> 3) & 1) * 16);

        float l_warp = 0.f;   // warp-local; reduced across warps at the end

        for (int i = 0; i < tcount; ++i) {
            const int s = i & 1;
            BSYNC(BAR_FULL0 + s, 256);
            const uint32_t sA = sbase + (s ? SMEM_A1 : SMEM_A0);

            // ---- load ALL A fragments once (held in regs) ----
            uint32_t afr[2][8][4];
#pragma unroll
            for (int mt = 0; mt < 2; ++mt)
#pragma unroll
                for (int k = 0; k < 8; ++k)
                    LDSM_X4(afr[mt][k], sA + (uint32_t)((cw * 32 + mt * 16) * PITCH_B + k * 32) + rowA_off);
            BARRIVE(BAR_DONE0 + s, 256);   // buf s free (A lives in regs)

            // ---- sweep B in 16-col chunks ----
            float sp[2][2] = {{0.f, 0.f}, {0.f, 0.f}};
#pragma unroll
            for (int nc = 0; nc < 8; ++nc) {
                float acc[2][2][4];
#pragma unroll
                for (int mt = 0; mt < 2; ++mt)
#pragma unroll
                    for (int nt = 0; nt < 2; ++nt)
#pragma unroll
                        for (int rr = 0; rr < 4; ++rr) acc[mt][nt][rr] = 0.f;
#pragma unroll
                for (int k = 0; k < 8; ++k) {
                    uint32_t bfr[4];
                    LDSM_X4(bfr, sW + (uint32_t)((nc * 16) * PITCH_B + k * 32) + rowB_off);
#pragma unroll
                    for (int mt = 0; mt < 2; ++mt) {
                        mma16816(acc[mt][0], afr[mt][k], bfr[0], bfr[1]);
                        mma16816(acc[mt][1], afr[mt][k], bfr[2], bfr[3]);
                    }
                }
#pragma unroll
                for (int mt = 0; mt < 2; ++mt)
#pragma unroll
                    for (int nt = 0; nt < 2; ++nt) {
                        const int colb = nc * 16 + nt * 8 + 2 * (lane & 3);
                        const float2 bv0 = biasv[colb];
                        const float2 bv1 = biasv[colb + 1];
#pragma unroll
                        for (int rr = 0; rr < 2; ++rr) {
                            float x0 = acc[mt][nt][rr * 2 + 0] + bv0.x;
                            float x1 = acc[mt][nt][rr * 2 + 1] + bv1.x;
                            float t0, t1;
                            asm("tanh.approx.f32 %0, %1;" : "=f"(t0) : "f"(x0));
                            asm("tanh.approx.f32 %0, %1;" : "=f"(t1) : "f"(x1));
                            sp[mt][rr] = fmaf(t0, bv0.y, sp[mt][rr]);
                            sp[mt][rr] = fmaf(t1, bv1.y, sp[mt][rr]);
                        }
                    }
            }

            // ---- scores -> smem (warp-local scatter) ----
#pragma unroll
            for (int mt = 0; mt < 2; ++mt)
#pragma unroll
                for (int rr = 0; rr < 2; ++rr) {
                    float v = sp[mt][rr];
                    v += __shfl_xor_sync(0xffffffffu, v, 1);
                    v += __shfl_xor_sync(0xffffffffu, v, 2);
                    if ((lane & 3) == 0)
                        s_score[cw * 32 + mt * 16 + rr * 8 + (lane >> 2)] = v;
                }
            __syncwarp();

            // ---- static-max softmax; publish into 4-slot ring (no ACC wait) ----
            const float p = __expf(s_score[ctid] - M_bound);
            s_w[(i & 3) * 128 + ctid] = p;

            // warp-local l accumulation (no block barrier)
            float ps = p;
#pragma unroll
            for (int o = 16; o; o >>= 1) ps += __shfl_xor_sync(0xffffffffu, ps, o);
            l_warp += ps;

            BARRIVE(BAR_SW0 + (i & 3), 256);
        }
        // final l reduction across 4 consumer warps
        if (lane == 0) s_red[4 + cw] = l_warp;
        BSYNC(BAR_CONS, 128);
        if (ctid == 0)
            g_pl[cta] = (s_red[4] + s_red[5]) + (s_red[6] + s_red[7]);
    }

    // ---------- last-CTA-per-batch combine ----------
    __threadfence();
    __syncthreads();
    int* s_flag = reinterpret_cast<int*>(smem + SMEM_RED);
    if (tid == 0) {
        int old = atomicAdd(&g_cnt[b], 1);
        s_flag[0] = (old == cpb - 1) ? 1 : 0;
    }
    __syncthreads();
    if (s_flag[0]) {
        __threadfence();
        if (tid < HID) {
            float L = 0.f, num = 0.f;
            for (int j = 0; j < cpb; ++j) {
                L   += __ldcg(&g_pl[base + j]);
                num += __ldcg(&g_pacc[(base + j) * HID + tid]);
            }
            out[b * HID + tid] = cur[b * HID + tid] + num / L;
        }
        if (tid == 0) g_cnt[b] = 0;   // reset for next graph replay
    }
}

// ============================================================
// Launch
// ============================================================
extern "C" void kernel_launch(void* const* d_in, const int* in_sizes, int n_in,
                              void* d_out, int out_size)
{
    (void)in_sizes; (void)n_in; (void)out_size;
    const float* cur  = (const float*)d_in[0];
    const float* hist = (const float*)d_in[1];
    const float* Wx   = (const float*)d_in[2];
    const float* Wxb  = (const float*)d_in[3];
    const float* Wh   = (const float*)d_in[4];
    const float* Whb  = (const float*)d_in[5];
    const float* vw   = (const float*)d_in[6];
    float* out = (float*)d_out;

    cudaFuncSetAttribute(attn_main_kernel,
                         cudaFuncAttributeMaxDynamicSharedMemorySize, SMEM_TOTAL);

    attn_main_kernel<<<NCTA, 256, SMEM_TOTAL>>>(hist, cur, Wx, Wxb, Wh, Whb, vw, out);
}